// round 13
// baseline (speedup 1.0000x reference)
#include <cuda_runtime.h>
#include <math.h>

#define Bz 32
#define Hd 1024
#define H4 4096
#define Tt 64
#define Ss 64
#define NB 128          // persistent grid size
#define KC 128          // k per chunk
#define NCH 8           // chunks per K=1024
#define HSTRIDE 132     // Hsm row stride (floats): conflict-free LDS.128
#define HBUF (32 * HSTRIDE)

typedef unsigned long long u64;

// ---------------- device scratch ----------------
__device__ float g_X0[Tt * Bz * H4];       // emb@Wih0^T + bih0 + bhh0
__device__ float g_Cw[Bz * Ss * Hd];       // contexts @ W_in
__device__ float g_sb[Bz * Ss];            // contexts . b_in
__device__ float g_h[2][2][Bz * Hd];       // [layer][parity] ping-pong hidden
__device__ float g_c[2][Bz * Hd];
__device__ float g_ctxall[Tt * Bz * Hd];
__device__ float g_h1all[Tt * Bz * Hd];
__device__ float g_Wt[3 * NB * 32768];     // [ph][jb][warp][chunk][kpair][4 rows]
__device__ unsigned g_bar_cnt = 0;
__device__ unsigned g_bar_sense = 0;

// dynamic smem carve (floats) for k_steps
#define SM_W   0        // 8 warps * 2 bufs * 512
#define SM_H   8192     // 2 * HBUF = 8448
#define SM_G   16640    // 32*33 = 1056
#define SM_TOT 17696

// ---------------- f32x2 helpers ----------------
__device__ __forceinline__ u64 ffma2(u64 a, u64 b, u64 c) {
    u64 d;
    asm("fma.rn.f32x2 %0, %1, %2, %3;" : "=l"(d) : "l"(a), "l"(b), "l"(c));
    return d;
}
__device__ __forceinline__ u64 dup2(float x) {
    u64 d; unsigned xi = __float_as_uint(x);
    asm("mov.b64 %0, {%1, %1};" : "=l"(d) : "r"(xi));
    return d;
}
__device__ __forceinline__ float2 unpack2(u64 d) {
    unsigned a, b;
    asm("mov.b64 {%0, %1}, %2;" : "=r"(a), "=r"(b) : "l"(d));
    return make_float2(__uint_as_float(a), __uint_as_float(b));
}
__device__ __forceinline__ float sigf(float x) { return 1.f / (1.f + expf(-x)); }

__device__ __forceinline__ void cpasync16(float* dst, const float* src) {
    unsigned d = (unsigned)__cvta_generic_to_shared(dst);
    asm volatile("cp.async.cg.shared.global [%0], [%1], 16;" :: "r"(d), "l"(src));
}

// ---------------- fused setup: init state + sb dot + weight transpose ----------
__global__ void k_setup(const float* __restrict__ h0, const float* __restrict__ c0,
                        const float* __restrict__ ctxs, const float* __restrict__ bin,
                        const float* __restrict__ Wih, const float* __restrict__ Whh) {
    int bx = blockIdx.x, tid = threadIdx.x;
    int jb = bx & (NB - 1), ph = bx >> 7;
    const float* src = (ph == 0) ? Whh : (ph == 1 ? Wih + (size_t)H4 * Hd
                                                  : Whh + (size_t)H4 * Hd);
    float* dst = g_Wt + ((size_t)ph * NB + jb) * 32768;
    int j0 = jb * 8;
    for (int i = tid; i < 32768; i += 256) {
        int e = i & 1, r = (i >> 1) & 3, kp = (i >> 3) & 63, c = (i >> 9) & 7, w = i >> 12;
        int row = 4 * w + r;
        int grow = (row >> 3) * Hd + j0 + (row & 7);
        int k = c * KC + kp * 2 + e;
        dst[i] = src[(size_t)grow * Hd + k];
    }
    if (bx < 256) {
        int idx = bx * 256 + tid;                 // < 65536
        int l = idx >> 15, r = idx & 32767;
        g_h[l][0][r] = h0[idx];
        g_c[l][r]    = c0[idx];
        int w = tid >> 5, lane = tid & 31;
        int row = bx * 8 + w;                     // < 2048
        const float* cr = ctxs + (size_t)row * Hd;
        float s = 0.f;
        for (int k = lane; k < Hd; k += 32) s += cr[k] * bin[k];
#pragma unroll
        for (int o = 16; o; o >>= 1) s += __shfl_xor_sync(~0u, s, o);
        if (!lane) g_sb[row] = s;
    }
}

// ---------------- P1: X0 = emb[tok] @ Wih0^T + biases ----------
__global__ void k_x0(const int* __restrict__ tokens, const float* __restrict__ emb,
                     const float* __restrict__ Wih, const float* __restrict__ bih,
                     const float* __restrict__ bhh) {
    __shared__ __align__(16) float Asm[32 * 33];
    __shared__ __align__(16) float Wsm[32 * 68];
    __shared__ int toks[32];
    int tid = threadIdx.x;
    int m0 = blockIdx.x * 32, n0 = blockIdx.y * 64;
    if (tid < 32) toks[tid] = tokens[m0 + tid];
    __syncthreads();
    int m = tid >> 3, q = tid & 7;
    u64 acc0 = 0, acc1 = 0, acc2 = 0, acc3 = 0;
    for (int k0 = 0; k0 < Hd; k0 += 32) {
        for (int idx = tid; idx < 1024; idx += 256) {
            int mm = idx >> 5, kk = idx & 31;
            Asm[kk * 33 + mm] = emb[(size_t)toks[mm] * Hd + k0 + kk];
        }
        for (int idx = tid; idx < 2048; idx += 256) {
            int nn = idx >> 5, kk = idx & 31;
            Wsm[kk * 68 + nn] = Wih[(size_t)(n0 + nn) * Hd + k0 + kk];
        }
        __syncthreads();
#pragma unroll
        for (int kk = 0; kk < 32; kk++) {
            u64 ad = dup2(Asm[kk * 33 + m]);
            const ulonglong2* wp = (const ulonglong2*)(Wsm + kk * 68 + q * 8);
            ulonglong2 w0 = wp[0], w1 = wp[1];
            acc0 = ffma2(w0.x, ad, acc0);
            acc1 = ffma2(w0.y, ad, acc1);
            acc2 = ffma2(w1.x, ad, acc2);
            acc3 = ffma2(w1.y, ad, acc3);
        }
        __syncthreads();
    }
    int row = m0 + m, nb = n0 + q * 8;
    float* dst = &g_X0[(size_t)row * H4 + nb];
    u64 accs[4] = {acc0, acc1, acc2, acc3};
#pragma unroll
    for (int j = 0; j < 4; j++) {
        float2 v = unpack2(accs[j]);
        int n = nb + 2 * j;
        dst[2 * j]     = v.x + bih[n] + bhh[n];
        dst[2 * j + 1] = v.y + bih[n + 1] + bhh[n + 1];
    }
}

// ---------------- P2: Cw = contexts @ W_in ----------------
__global__ void k_cw(const float* __restrict__ ctxs, const float* __restrict__ Win) {
    __shared__ __align__(16) float Asm[32 * 33];
    __shared__ __align__(16) float Wsm[32 * 68];
    int tid = threadIdx.x;
    int m0 = blockIdx.x * 32, n0 = blockIdx.y * 64;
    int m = tid >> 3, q = tid & 7;
    u64 acc0 = 0, acc1 = 0, acc2 = 0, acc3 = 0;
    for (int r0 = 0; r0 < Hd; r0 += 32) {
        for (int idx = tid; idx < 1024; idx += 256) {
            int mm = idx >> 5, kk = idx & 31;
            Asm[kk * 33 + mm] = ctxs[(size_t)(m0 + mm) * Hd + r0 + kk];
        }
        for (int idx = tid; idx < 2048; idx += 256) {
            int nn = idx & 63, kk = idx >> 6;
            Wsm[kk * 68 + nn] = Win[(size_t)(r0 + kk) * Hd + n0 + nn];
        }
        __syncthreads();
#pragma unroll
        for (int kk = 0; kk < 32; kk++) {
            u64 ad = dup2(Asm[kk * 33 + m]);
            const ulonglong2* wp = (const ulonglong2*)(Wsm + kk * 68 + q * 8);
            ulonglong2 w0 = wp[0], w1 = wp[1];
            acc0 = ffma2(w0.x, ad, acc0);
            acc1 = ffma2(w0.y, ad, acc1);
            acc2 = ffma2(w1.x, ad, acc2);
            acc3 = ffma2(w1.y, ad, acc3);
        }
        __syncthreads();
    }
    int row = m0 + m, nb = n0 + q * 8;
    float* dst = &g_Cw[(size_t)row * Hd + nb];
    u64 accs[4] = {acc0, acc1, acc2, acc3};
#pragma unroll
    for (int j = 0; j < 4; j++) {
        float2 v = unpack2(accs[j]);
        dst[2 * j]     = v.x;
        dst[2 * j + 1] = v.y;
    }
}

// ---------------- grid barrier (sense-reversing, self-resetting) ----------------
__device__ __forceinline__ void gridbar(int* s_lsense) {
    __syncthreads();
    if (threadIdx.x == 0) {
        asm volatile("fence.acq_rel.gpu;" ::: "memory");
        int s = *s_lsense ^ 1;
        *s_lsense = s;
        unsigned old = atomicAdd(&g_bar_cnt, 1);
        if (old == NB - 1) {
            g_bar_cnt = 0;
            asm volatile("fence.acq_rel.gpu;" ::: "memory");
            *(volatile unsigned*)&g_bar_sense = (unsigned)s;
        } else {
            while ((int)(*(volatile unsigned*)&g_bar_sense) != s) __nanosleep(32);
        }
        asm volatile("fence.acq_rel.gpu;" ::: "memory");
    }
    __syncthreads();
}

// ---------------- streamed GEMM phase (f32x2 over K, warp-autonomous weights) ----
__device__ __forceinline__ void phase(const float* __restrict__ Wtp,
                                      const float* __restrict__ Sv,
                                      float* __restrict__ Wsm,
                                      float* __restrict__ Hsm,
                                      int tid, u64* acc) {
    int w = tid >> 5, lane = tid & 31;
    int b = lane;
    int bs = tid >> 3, c8 = tid & 7;
    const float* wsrc = Wtp + w * 4096;
    float* wb0 = Wsm + w * 1024;
    float* wb1 = wb0 + 512;
    const float* hsrc = Sv + (size_t)bs * Hd + c8 * 16;

    float4 rB0 = *(const float4*)(hsrc + 0);
    float4 rB1 = *(const float4*)(hsrc + 4);
    float4 rB2 = *(const float4*)(hsrc + 8);
    float4 rB3 = *(const float4*)(hsrc + 12);
    {
        float* hd = Hsm + bs * HSTRIDE + c8 * 16;
        ((float4*)hd)[0] = rB0; ((float4*)(hd + 4))[0] = rB1;
        ((float4*)(hd + 8))[0] = rB2; ((float4*)(hd + 12))[0] = rB3;
    }
    rB0 = *(const float4*)(hsrc + KC + 0);
    rB1 = *(const float4*)(hsrc + KC + 4);
    rB2 = *(const float4*)(hsrc + KC + 8);
    rB3 = *(const float4*)(hsrc + KC + 12);
#pragma unroll
    for (int i = 0; i < 4; i++) cpasync16(wb0 + lane * 16 + 4 * i, wsrc + lane * 16 + 4 * i);
    asm volatile("cp.async.commit_group;");
#pragma unroll
    for (int i = 0; i < 4; i++) cpasync16(wb1 + lane * 16 + 4 * i, wsrc + 512 + lane * 16 + 4 * i);
    asm volatile("cp.async.commit_group;");
    __syncthreads();

#pragma unroll 1
    for (int c = 0; c < NCH; c++) {
        int buf = c & 1;
        if (c + 1 < NCH) {
            float* hd = Hsm + ((c + 1) & 1) * HBUF + bs * HSTRIDE + c8 * 16;
            ((float4*)hd)[0] = rB0; ((float4*)(hd + 4))[0] = rB1;
            ((float4*)(hd + 8))[0] = rB2; ((float4*)(hd + 12))[0] = rB3;
        }
        if (c + 2 < NCH) {
            const float* s = hsrc + (c + 2) * KC;
            rB0 = *(const float4*)(s + 0); rB1 = *(const float4*)(s + 4);
            rB2 = *(const float4*)(s + 8); rB3 = *(const float4*)(s + 12);
        }
        if (c < NCH - 1) asm volatile("cp.async.wait_group 1;");
        else             asm volatile("cp.async.wait_group 0;");
        __syncwarp();
        const u64* Wb = (const u64*)((buf ? wb1 : wb0));
        const float* Hb = Hsm + buf * HBUF + b * HSTRIDE;
#pragma unroll
        for (int kq = 0; kq < 32; kq++) {
            ulonglong2 h2 = *(const ulonglong2*)(Hb + kq * 4);
            ulonglong2 wA = *(const ulonglong2*)(Wb + (2 * kq) * 4);
            ulonglong2 wB = *(const ulonglong2*)(Wb + (2 * kq) * 4 + 2);
            ulonglong2 wC = *(const ulonglong2*)(Wb + (2 * kq + 1) * 4);
            ulonglong2 wD = *(const ulonglong2*)(Wb + (2 * kq + 1) * 4 + 2);
            acc[0] = ffma2(wA.x, h2.x, acc[0]);
            acc[1] = ffma2(wA.y, h2.x, acc[1]);
            acc[2] = ffma2(wB.x, h2.x, acc[2]);
            acc[3] = ffma2(wB.y, h2.x, acc[3]);
            acc[0] = ffma2(wC.x, h2.y, acc[0]);
            acc[1] = ffma2(wC.y, h2.y, acc[1]);
            acc[2] = ffma2(wD.x, h2.y, acc[2]);
            acc[3] = ffma2(wD.y, h2.y, acc[3]);
        }
        __syncwarp();
        if (c + 2 < NCH) {
            float* wbd = buf ? wb1 : wb0;
#pragma unroll
            for (int i = 0; i < 4; i++)
                cpasync16(wbd + lane * 16 + 4 * i, wsrc + (c + 2) * 512 + lane * 16 + 4 * i);
            asm volatile("cp.async.commit_group;");
        }
        __syncthreads();
    }
}

// ---------------- persistent recurrence kernel: TWO barriers per step (proven) ----
__global__ void __launch_bounds__(256, 1)
k_steps(const float* __restrict__ bih, const float* __restrict__ bhh) {
    extern __shared__ float dsm[];
    float* Wsm  = dsm + SM_W;
    float* Hsm  = dsm + SM_H;
    float* Gsm  = dsm + SM_G;
    __shared__ int s_lsense;

    int tid = threadIdx.x;
    int jb = blockIdx.x, j0 = jb * 8;
    if (tid == 0) s_lsense = 0;

    int b = tid & 31, r0 = (tid >> 5) * 4;
    int gr0 = (r0 >> 3) * Hd + j0 + (r0 & 7);
    int jj = tid >> 5, b2 = tid & 31;
    int jcell = j0 + jj;
    float c0r = g_c[0][b2 * Hd + jcell];
    float c1r = g_c[1][b2 * Hd + jcell];
    const float* bihL = bih + H4;
    const float* bhhL = bhh + H4;
    float4 bv1;
    bv1.x = bihL[gr0]     + bhhL[gr0];
    bv1.y = bihL[gr0 + 1] + bhhL[gr0 + 1];
    bv1.z = bihL[gr0 + 2] + bhhL[gr0 + 2];
    bv1.w = bihL[gr0 + 3] + bhhL[gr0 + 3];

    const float* Wt0  = g_Wt + ((size_t)0 * NB + jb) * 32768;
    const float* Wt1i = g_Wt + ((size_t)1 * NB + jb) * 32768;
    const float* Wt1h = g_Wt + ((size_t)2 * NB + jb) * 32768;
    __syncthreads();

    for (int t = 0; t < Tt; t++) {
        int p = t & 1;
        // ---------- layer 0 ----------
        const float* X0t = g_X0 + (size_t)t * Bz * H4;   // prefetch: overlap L2 latency
        float4 x0v = *(const float4*)(X0t + (size_t)b * H4 + gr0);
        u64 acc[4] = {0, 0, 0, 0};
        phase(Wt0, g_h[0][p], Wsm, Hsm, tid, acc);
        {
            float2 q0 = unpack2(acc[0]), q1 = unpack2(acc[1]);
            float2 q2 = unpack2(acc[2]), q3 = unpack2(acc[3]);
            Gsm[(r0 + 0) * 33 + b] = q0.x + q0.y + x0v.x;
            Gsm[(r0 + 1) * 33 + b] = q1.x + q1.y + x0v.y;
            Gsm[(r0 + 2) * 33 + b] = q2.x + q2.y + x0v.z;
            Gsm[(r0 + 3) * 33 + b] = q3.x + q3.y + x0v.w;
        }
        __syncthreads();
        {
            float gi = Gsm[jj * 33 + b2];
            float gf = Gsm[(8 + jj) * 33 + b2];
            float gg = Gsm[(16 + jj) * 33 + b2];
            float go = Gsm[(24 + jj) * 33 + b2];
            float cn = sigf(gf) * c0r + sigf(gi) * tanhf(gg);
            c0r = cn;
            g_h[0][p ^ 1][b2 * Hd + jcell] = sigf(go) * tanhf(cn);
        }
        gridbar(&s_lsense);                      // barrier A

        // ---------- layer 1 ----------
        acc[0] = acc[1] = acc[2] = acc[3] = 0;
        phase(Wt1i, g_h[0][p ^ 1], Wsm, Hsm, tid, acc);
        phase(Wt1h, g_h[1][p],     Wsm, Hsm, tid, acc);
        {
            float2 q0 = unpack2(acc[0]), q1 = unpack2(acc[1]);
            float2 q2 = unpack2(acc[2]), q3 = unpack2(acc[3]);
            Gsm[(r0 + 0) * 33 + b] = q0.x + q0.y + bv1.x;
            Gsm[(r0 + 1) * 33 + b] = q1.x + q1.y + bv1.y;
            Gsm[(r0 + 2) * 33 + b] = q2.x + q2.y + bv1.z;
            Gsm[(r0 + 3) * 33 + b] = q3.x + q3.y + bv1.w;
        }
        __syncthreads();
        {
            float gi = Gsm[jj * 33 + b2];
            float gf = Gsm[(8 + jj) * 33 + b2];
            float gg = Gsm[(16 + jj) * 33 + b2];
            float go = Gsm[(24 + jj) * 33 + b2];
            float cn = sigf(gf) * c1r + sigf(gi) * tanhf(gg);
            c1r = cn;
            float hv = sigf(go) * tanhf(cn);
            g_h[1][p ^ 1][b2 * Hd + jcell] = hv;
            g_h1all[(size_t)t * Bz * Hd + b2 * Hd + jcell] = hv;
        }
        gridbar(&s_lsense);                      // barrier B (restored, proven in R8)
    }
    g_c[0][b2 * Hd + jcell] = c0r;
    g_c[1][b2 * Hd + jcell] = c1r;
}

// ---------------- deferred attention: scores + softmax + context, per (t,b) -------
__global__ void k_attn_post(const float* __restrict__ ctxs) {
    __shared__ __align__(16) float hsm[1024];
    __shared__ float ssm[64], wsm[64];
    int bx = blockIdx.x, tid = threadIdx.x;
    int t = bx >> 5, bb = bx & 31;
    const float* h1 = g_h1all + (size_t)(t * Bz + bb) * Hd;
    for (int i = tid; i < 1024; i += 256) hsm[i] = h1[i];
    __syncthreads();
    int wq = tid >> 5, lane = tid & 31;
    const float4* h4 = (const float4*)hsm;
#pragma unroll
    for (int si = 0; si < 8; si++) {
        int s = wq * 8 + si;
        const float4* cw4 = (const float4*)(g_Cw + (size_t)(bb * Ss + s) * Hd);
        float a = 0.f;
#pragma unroll
        for (int i = 0; i < 8; i++) {
            float4 cv = cw4[lane + 32 * i];
            float4 hv = h4[lane + 32 * i];
            a += cv.x * hv.x + cv.y * hv.y + cv.z * hv.z + cv.w * hv.w;
        }
#pragma unroll
        for (int o = 16; o; o >>= 1) a += __shfl_xor_sync(~0u, a, o);
        if (!lane) ssm[s] = a + g_sb[bb * Ss + s];
    }
    __syncthreads();
    if (tid == 0) {
        float mx = ssm[0];
        for (int s = 1; s < 64; s++) mx = fmaxf(mx, ssm[s]);
        float sum = 0.f;
        for (int s = 0; s < 64; s++) { float e = expf(ssm[s] - mx); wsm[s] = e; sum += e; }
        float inv = 1.f / sum;
        for (int s = 0; s < 64; s++) wsm[s] *= inv;
    }
    __syncthreads();
    const float4* c4 = (const float4*)(ctxs + (size_t)bb * Ss * Hd);
    float4 acc = make_float4(0.f, 0.f, 0.f, 0.f);
    for (int s = 0; s < 64; s++) {
        float wv = wsm[s];
        float4 cv = c4[s * 256 + tid];
        acc.x += wv * cv.x; acc.y += wv * cv.y; acc.z += wv * cv.z; acc.w += wv * cv.w;
    }
    ((float4*)(g_ctxall + (size_t)(t * Bz + bb) * Hd))[tid] = acc;
}

// ---------------- final big GEMM: out = tanh([ctx, h1] @ Wout^T + b) ----------
__global__ void k_out_big(const float* __restrict__ Wout, const float* __restrict__ bout,
                          float* __restrict__ out) {
    __shared__ __align__(16) float Asm[32 * 33];
    __shared__ __align__(16) float Wsm[32 * 68];
    int tid = threadIdx.x;
    int m0 = blockIdx.x * 32, n0 = blockIdx.y * 64;
    int m = tid >> 3, q = tid & 7;
    u64 acc0 = 0, acc1 = 0, acc2 = 0, acc3 = 0;
    for (int k0 = 0; k0 < 2 * Hd; k0 += 32) {
        for (int idx = tid; idx < 1024; idx += 256) {
            int mm = idx >> 5, kk = idx & 31;
            int k = k0 + kk;
            float v = (k < Hd) ? g_ctxall[(size_t)(m0 + mm) * Hd + k]
                               : g_h1all[(size_t)(m0 + mm) * Hd + k - Hd];
            Asm[kk * 33 + mm] = v;
        }
        for (int idx = tid; idx < 2048; idx += 256) {
            int nn = idx >> 5, kk = idx & 31;
            Wsm[kk * 68 + nn] = Wout[(size_t)(n0 + nn) * (2 * Hd) + k0 + kk];
        }
        __syncthreads();
#pragma unroll
        for (int kk = 0; kk < 32; kk++) {
            u64 ad = dup2(Asm[kk * 33 + m]);
            const ulonglong2* wp = (const ulonglong2*)(Wsm + kk * 68 + q * 8);
            ulonglong2 w0 = wp[0], w1 = wp[1];
            acc0 = ffma2(w0.x, ad, acc0);
            acc1 = ffma2(w0.y, ad, acc1);
            acc2 = ffma2(w1.x, ad, acc2);
            acc3 = ffma2(w1.y, ad, acc3);
        }
        __syncthreads();
    }
    int row = m0 + m, nb = n0 + q * 8;
    float* dst = out + (size_t)row * Hd + nb;
    u64 accs[4] = {acc0, acc1, acc2, acc3};
#pragma unroll
    for (int j = 0; j < 4; j++) {
        float2 v = unpack2(accs[j]);
        int n = nb + 2 * j;
        dst[2 * j]     = tanhf(v.x + bout[n]);
        dst[2 * j + 1] = tanhf(v.y + bout[n + 1]);
    }
}

// ---------------- hT, cT tail ----------
__global__ void k_tail(float* __restrict__ out, int out_size) {
    int idx = blockIdx.x * 256 + threadIdx.x;
    int base = Tt * Bz * Hd;
    if (idx < 2 * Bz * Hd) {
        int l = idx >> 15, r = idx & 32767;
        int o = base + idx;
        if (o < out_size) out[o] = g_h[l][0][r];
    } else {
        int jx = idx - 2 * Bz * Hd;
        int l = jx >> 15, r = jx & 32767;
        int o = base + 2 * Bz * Hd + jx;
        if (o < out_size) out[o] = g_c[l][r];
    }
}

extern "C" void kernel_launch(void* const* d_in, const int* in_sizes, int n_in,
                              void* d_out, int out_size) {
    const int*   tokens   = (const int*)d_in[0];
    const float* h0       = (const float*)d_in[1];
    const float* c0       = (const float*)d_in[2];
    const float* contexts = (const float*)d_in[3];
    const float* emb      = (const float*)d_in[4];
    const float* W_ih     = (const float*)d_in[5];
    const float* W_hh     = (const float*)d_in[6];
    const float* b_ih     = (const float*)d_in[7];
    const float* b_hh     = (const float*)d_in[8];
    const float* W_in     = (const float*)d_in[9];
    const float* b_in     = (const float*)d_in[10];
    const float* W_out    = (const float*)d_in[11];
    const float* b_out    = (const float*)d_in[12];
    float* out = (float*)d_out;

    // unconditional, idempotent (no static guards allowed)
    cudaFuncSetAttribute(k_steps, cudaFuncAttributeMaxDynamicSharedMemorySize,
                         SM_TOT * 4);

    k_setup<<<3 * NB, 256>>>(h0, c0, contexts, b_in, W_ih, W_hh);          // 1
    k_x0<<<dim3(64, 64), 256>>>(tokens, emb, W_ih, b_ih, b_hh);            // 2
    k_cw<<<dim3(64, 16), 256>>>(contexts, W_in);                           // 3
    k_steps<<<NB, 256, SM_TOT * 4>>>(b_ih, b_hh);                          // 4 <- ncu
    k_attn_post<<<Tt * Bz, 256>>>(contexts);                               // 5
    k_out_big<<<dim3(64, 16), 256>>>(W_out, b_out, out);                   // 6
    k_tail<<<512, 256>>>(out, out_size);                                   // 7
}

// round 14
// speedup vs baseline: 1.2967x; 1.2967x over previous
#include <cuda_runtime.h>
#include <math.h>

#define Bz 32
#define Hd 1024
#define H4 4096
#define Tt 64
#define Ss 64
#define NB 128

typedef unsigned long long u64;

__device__ float g_X0T[Tt * H4 * Bz];      // [t][gate-row n][b]
__device__ float g_Cw[Bz * Ss * Hd];
__device__ float g_sb[Bz * Ss];
__device__ float g_h[2][2][Bz * Hd];
__device__ float g_c[2][Bz * Hd];
__device__ float g_ctxall[Tt * Bz * Hd];
__device__ float g_h1all[Tt * Bz * Hd];
__device__ float g_Wt[3 * NB * 32768];     // [ph][jb][qc16][kq16][i4][r8][e4]
__device__ unsigned g_bar_cnt = 0;
__device__ unsigned g_bar_sense = 0;

// smem floats: W 4q*2*2048=16384 | H 4q*2*2176=17408 | G 4q*1056=4224
#define SM_W 0
#define SM_H 16384
#define SM_G 33792
#define SM_TOT 38016

__device__ __forceinline__ u64 ffma2(u64 a, u64 b, u64 c) {
    u64 d;
    asm("fma.rn.f32x2 %0, %1, %2, %3;" : "=l"(d) : "l"(a), "l"(b), "l"(c));
    return d;
}
__device__ __forceinline__ u64 dup2(float x) {
    u64 d; unsigned xi = __float_as_uint(x);
    asm("mov.b64 %0, {%1, %1};" : "=l"(d) : "r"(xi));
    return d;
}
__device__ __forceinline__ float2 unpack2(u64 d) {
    unsigned a, b;
    asm("mov.b64 {%0, %1}, %2;" : "=r"(a), "=r"(b) : "l"(d));
    return make_float2(__uint_as_float(a), __uint_as_float(b));
}
__device__ __forceinline__ float sigf(float x) { return 1.f / (1.f + expf(-x)); }
__device__ __forceinline__ void cpasync16(float* dst, const float* src) {
    unsigned d = (unsigned)__cvta_generic_to_shared(dst);
    asm volatile("cp.async.cg.shared.global [%0], [%1], 16;" :: "r"(d), "l"(src));
}

// ---------------- setup: init + sb + weight transpose (new tiled layout) ---------
__global__ void k_setup(const float* __restrict__ h0, const float* __restrict__ c0,
                        const float* __restrict__ ctxs, const float* __restrict__ bin,
                        const float* __restrict__ Wih, const float* __restrict__ Whh) {
    int bx = blockIdx.x, tid = threadIdx.x;
    int jb = bx & (NB - 1), ph = bx >> 7;
    const float* src = (ph == 0) ? Whh : (ph == 1 ? Wih + (size_t)H4 * Hd
                                                  : Whh + (size_t)H4 * Hd);
    float* dst = g_Wt + ((size_t)ph * NB + jb) * 32768;
    int j0 = jb * 8;
    for (int f = tid; f < 32768; f += 256) {
        int e = f & 3, kpar = e & 1, sel = e >> 1;
        int r8 = (f >> 2) & 7;
        int i4 = (f >> 5) & 3, kp = i4 & 1, rp = i4 >> 1;
        int kq = (f >> 7) & 15;
        int qc = f >> 11;
        int row32 = 4 * r8 + 2 * rp + sel;
        int k = qc * 64 + kq * 4 + kp * 2 + kpar;
        int grow = (row32 >> 3) * Hd + j0 + (row32 & 7);
        dst[f] = src[(size_t)grow * Hd + k];
    }
    if (bx < 256) {
        int idx = bx * 256 + tid;
        int l = idx >> 15, r = idx & 32767;
        g_h[l][0][r] = h0[idx];
        g_c[l][r]    = c0[idx];
        int w = tid >> 5, lane = tid & 31;
        int row = bx * 8 + w;
        const float* cr = ctxs + (size_t)row * Hd;
        float s = 0.f;
        for (int k = lane; k < Hd; k += 32) s += cr[k] * bin[k];
#pragma unroll
        for (int o = 16; o; o >>= 1) s += __shfl_xor_sync(~0u, s, o);
        if (!lane) g_sb[row] = s;
    }
}

// ---------------- X0T[t][n][b] = emb[tok].Wih0[n,:] + biases ----------
__global__ void k_x0(const int* __restrict__ tokens, const float* __restrict__ emb,
                     const float* __restrict__ Wih, const float* __restrict__ bih,
                     const float* __restrict__ bhh) {
    __shared__ __align__(16) float Asm[32 * 33];
    __shared__ __align__(16) float Wsm[32 * 68];
    __shared__ int toks[32];
    int tid = threadIdx.x;
    int m0 = blockIdx.x * 32, n0 = blockIdx.y * 64;
    if (tid < 32) toks[tid] = tokens[m0 + tid];
    __syncthreads();
    int m = tid >> 3, q = tid & 7;
    u64 acc0 = 0, acc1 = 0, acc2 = 0, acc3 = 0;
    for (int k0 = 0; k0 < Hd; k0 += 32) {
        for (int idx = tid; idx < 1024; idx += 256) {
            int mm = idx >> 5, kk = idx & 31;
            Asm[kk * 33 + mm] = emb[(size_t)toks[mm] * Hd + k0 + kk];
        }
        for (int idx = tid; idx < 2048; idx += 256) {
            int nn = idx >> 5, kk = idx & 31;
            Wsm[kk * 68 + nn] = Wih[(size_t)(n0 + nn) * Hd + k0 + kk];
        }
        __syncthreads();
#pragma unroll
        for (int kk = 0; kk < 32; kk++) {
            u64 ad = dup2(Asm[kk * 33 + m]);
            const ulonglong2* wp = (const ulonglong2*)(Wsm + kk * 68 + q * 8);
            ulonglong2 w0 = wp[0], w1 = wp[1];
            acc0 = ffma2(w0.x, ad, acc0);
            acc1 = ffma2(w0.y, ad, acc1);
            acc2 = ffma2(w1.x, ad, acc2);
            acc3 = ffma2(w1.y, ad, acc3);
        }
        __syncthreads();
    }
    int row = m0 + m, nb = n0 + q * 8;
    int t = row >> 5, b = row & 31;
    float* dstT = g_X0T + (size_t)t * (H4 * Bz) + b;
    u64 accs[4] = {acc0, acc1, acc2, acc3};
#pragma unroll
    for (int j = 0; j < 4; j++) {
        float2 v = unpack2(accs[j]);
        int n = nb + 2 * j;
        dstT[(size_t)n * 32]       = v.x + bih[n] + bhh[n];
        dstT[(size_t)(n + 1) * 32] = v.y + bih[n + 1] + bhh[n + 1];
    }
}

// ---------------- Cw = contexts @ W_in ----------------
__global__ void k_cw(const float* __restrict__ ctxs, const float* __restrict__ Win) {
    __shared__ __align__(16) float Asm[32 * 33];
    __shared__ __align__(16) float Wsm[32 * 68];
    int tid = threadIdx.x;
    int m0 = blockIdx.x * 32, n0 = blockIdx.y * 64;
    int m = tid >> 3, q = tid & 7;
    u64 acc0 = 0, acc1 = 0, acc2 = 0, acc3 = 0;
    for (int r0 = 0; r0 < Hd; r0 += 32) {
        for (int idx = tid; idx < 1024; idx += 256) {
            int mm = idx >> 5, kk = idx & 31;
            Asm[kk * 33 + mm] = ctxs[(size_t)(m0 + mm) * Hd + r0 + kk];
        }
        for (int idx = tid; idx < 2048; idx += 256) {
            int nn = idx & 63, kk = idx >> 6;
            Wsm[kk * 68 + nn] = Win[(size_t)(r0 + kk) * Hd + n0 + nn];
        }
        __syncthreads();
#pragma unroll
        for (int kk = 0; kk < 32; kk++) {
            u64 ad = dup2(Asm[kk * 33 + m]);
            const ulonglong2* wp = (const ulonglong2*)(Wsm + kk * 68 + q * 8);
            ulonglong2 w0 = wp[0], w1 = wp[1];
            acc0 = ffma2(w0.x, ad, acc0);
            acc1 = ffma2(w0.y, ad, acc1);
            acc2 = ffma2(w1.x, ad, acc2);
            acc3 = ffma2(w1.y, ad, acc3);
        }
        __syncthreads();
    }
    int row = m0 + m, nb = n0 + q * 8;
    float* dst = &g_Cw[(size_t)row * Hd + nb];
    u64 accs[4] = {acc0, acc1, acc2, acc3};
#pragma unroll
    for (int j = 0; j < 4; j++) {
        float2 v = unpack2(accs[j]);
        dst[2 * j]     = v.x;
        dst[2 * j + 1] = v.y;
    }
}

// ---------------- grid barrier ----------------
__device__ __forceinline__ void gridbar(int* s_lsense) {
    __syncthreads();
    if (threadIdx.x == 0) {
        asm volatile("fence.acq_rel.gpu;" ::: "memory");
        int s = *s_lsense ^ 1;
        *s_lsense = s;
        unsigned old = atomicAdd(&g_bar_cnt, 1);
        if (old == NB - 1) {
            g_bar_cnt = 0;
            asm volatile("fence.acq_rel.gpu;" ::: "memory");
            *(volatile unsigned*)&g_bar_sense = (unsigned)s;
        } else {
            while ((int)(*(volatile unsigned*)&g_bar_sense) != s) __nanosleep(32);
        }
        asm volatile("fence.acq_rel.gpu;" ::: "memory");
    }
    __syncthreads();
}

// ---------------- 4x4-tile GEMM phase, 4-way K-split ----------------
__device__ __forceinline__ void phase4(const float* __restrict__ Wtp,
                                       const float* __restrict__ Sv,
                                       float* __restrict__ dsm,
                                       int tid, u64* acc) {
    int q = tid >> 6, t64 = tid & 63;
    int rslot = t64 >> 3, bslot = t64 & 7;
    float* Wq = dsm + SM_W + q * 4096;
    float* Hq = dsm + SM_H + q * 4352;
    const float* wsrcQ = Wtp + q * 8192;
    const float* hsrcQ = Sv + q * 256;
#pragma unroll
    for (int c0 = 0; c0 < 2; c0++) {
        float* wd = Wq + c0 * 2048;
        float* hd = Hq + c0 * 2176;
        const float* ws = wsrcQ + c0 * 2048;
#pragma unroll
        for (int j = 0; j < 8; j++) {
            int gi = t64 + 64 * j;
            cpasync16(wd + gi * 4, ws + gi * 4);
            int bs = gi >> 4, qd = gi & 15;
            cpasync16(hd + bs * 68 + qd * 4, hsrcQ + (size_t)bs * Hd + c0 * 64 + qd * 4);
        }
        asm volatile("cp.async.commit_group;");
    }
#pragma unroll 1
    for (int c = 0; c < 4; c++) {
        int buf = c & 1;
        if (c < 3) asm volatile("cp.async.wait_group 1;");
        else       asm volatile("cp.async.wait_group 0;");
        __syncthreads();
        const float* wr  = Wq + buf * 2048 + rslot * 4;
        const float* hb0 = Hq + buf * 2176 + bslot * 68;
#pragma unroll
        for (int kq = 0; kq < 16; kq++) {
            ulonglong2 Wa = *(const ulonglong2*)(wr + kq * 128);
            ulonglong2 Wb = *(const ulonglong2*)(wr + kq * 128 + 32);
            ulonglong2 Wc = *(const ulonglong2*)(wr + kq * 128 + 64);
            ulonglong2 Wd = *(const ulonglong2*)(wr + kq * 128 + 96);
#pragma unroll
            for (int bb = 0; bb < 4; bb++) {
                ulonglong2 Hv = *(const ulonglong2*)(hb0 + bb * 544 + kq * 4);
                acc[bb]      = ffma2(Wa.x, Hv.x, acc[bb]);
                acc[bb]      = ffma2(Wb.x, Hv.y, acc[bb]);
                acc[4 + bb]  = ffma2(Wa.y, Hv.x, acc[4 + bb]);
                acc[4 + bb]  = ffma2(Wb.y, Hv.y, acc[4 + bb]);
                acc[8 + bb]  = ffma2(Wc.x, Hv.x, acc[8 + bb]);
                acc[8 + bb]  = ffma2(Wd.x, Hv.y, acc[8 + bb]);
                acc[12 + bb] = ffma2(Wc.y, Hv.x, acc[12 + bb]);
                acc[12 + bb] = ffma2(Wd.y, Hv.y, acc[12 + bb]);
            }
        }
        __syncthreads();
        if (c + 2 < 4) {
            float* wd = Wq + buf * 2048;
            float* hd = Hq + buf * 2176;
            const float* ws = wsrcQ + (c + 2) * 2048;
#pragma unroll
            for (int j = 0; j < 8; j++) {
                int gi = t64 + 64 * j;
                cpasync16(wd + gi * 4, ws + gi * 4);
                int bs = gi >> 4, qd = gi & 15;
                cpasync16(hd + bs * 68 + qd * 4,
                          hsrcQ + (size_t)bs * Hd + (c + 2) * 64 + qd * 4);
            }
            asm volatile("cp.async.commit_group;");
        }
    }
}

// store 16 partials into this quarter's Gsm region
__device__ __forceinline__ void reduce_store(float* __restrict__ dsm, int tid, u64* acc) {
    int q = tid >> 6, t64 = tid & 63;
    int rslot = t64 >> 3, bslot = t64 & 7;
    float* Gq = dsm + SM_G + q * 1056;
#pragma unroll
    for (int rr = 0; rr < 4; rr++)
#pragma unroll
        for (int bb = 0; bb < 4; bb++) {
            float2 v = unpack2(acc[rr * 4 + bb]);
            Gq[(rslot * 4 + rr) * 33 + bslot + 8 * bb] = v.x + v.y;
        }
}

// ---------------- persistent recurrence kernel ----------------
__global__ void __launch_bounds__(256, 1)
k_steps(const float* __restrict__ bih, const float* __restrict__ bhh) {
    extern __shared__ float dsm[];
    __shared__ int s_lsense;
    int tid = threadIdx.x;
    int jb = blockIdx.x, j0 = jb * 8;
    if (tid == 0) s_lsense = 0;

    int jj = tid >> 5, b2 = tid & 31;
    int jcell = j0 + jj;
    float c0r = g_c[0][b2 * Hd + jcell];
    float c1r = g_c[1][b2 * Hd + jcell];
    const float* bihL = bih + H4;
    const float* bhhL = bhh + H4;
    float bvg[4];
#pragma unroll
    for (int g = 0; g < 4; g++)
        bvg[g] = bihL[g * Hd + j0 + jj] + bhhL[g * Hd + j0 + jj];

    const float* Wt0  = g_Wt + ((size_t)0 * NB + jb) * 32768;
    const float* Wt1i = g_Wt + ((size_t)1 * NB + jb) * 32768;
    const float* Wt1h = g_Wt + ((size_t)2 * NB + jb) * 32768;
    float* Gsm = dsm + SM_G;
    __syncthreads();

    for (int t = 0; t < Tt; t++) {
        int p = t & 1;
        // ---------- layer 0 ----------
        const float* X0t = g_X0T + (size_t)t * (H4 * Bz);
        float x0g[4];
#pragma unroll
        for (int g = 0; g < 4; g++)
            x0g[g] = X0t[(size_t)(g * Hd + j0 + jj) * 32 + b2];
        u64 acc[16];
#pragma unroll
        for (int i = 0; i < 16; i++) acc[i] = 0;
        phase4(Wt0, g_h[0][p], dsm, tid, acc);
        reduce_store(dsm, tid, acc);
        __syncthreads();
        {
            float gt[4];
#pragma unroll
            for (int g = 0; g < 4; g++) {
                int off = (g * 8 + jj) * 33 + b2;
                gt[g] = Gsm[off] + Gsm[1056 + off] + Gsm[2112 + off]
                      + Gsm[3168 + off] + x0g[g];
            }
            float cn = sigf(gt[1]) * c0r + sigf(gt[0]) * tanhf(gt[2]);
            c0r = cn;
            g_h[0][p ^ 1][b2 * Hd + jcell] = sigf(gt[3]) * tanhf(cn);
        }
        gridbar(&s_lsense);                      // barrier A

        // ---------- layer 1 ----------
#pragma unroll
        for (int i = 0; i < 16; i++) acc[i] = 0;
        phase4(Wt1i, g_h[0][p ^ 1], dsm, tid, acc);
        phase4(Wt1h, g_h[1][p],     dsm, tid, acc);
        reduce_store(dsm, tid, acc);
        __syncthreads();
        {
            float gt[4];
#pragma unroll
            for (int g = 0; g < 4; g++) {
                int off = (g * 8 + jj) * 33 + b2;
                gt[g] = Gsm[off] + Gsm[1056 + off] + Gsm[2112 + off]
                      + Gsm[3168 + off] + bvg[g];
            }
            float cn = sigf(gt[1]) * c1r + sigf(gt[0]) * tanhf(gt[2]);
            c1r = cn;
            float hv = sigf(gt[3]) * tanhf(cn);
            g_h[1][p ^ 1][b2 * Hd + jcell] = hv;
            g_h1all[(size_t)t * Bz * Hd + b2 * Hd + jcell] = hv;
        }
        gridbar(&s_lsense);                      // barrier B
    }
    g_c[0][b2 * Hd + jcell] = c0r;
    g_c[1][b2 * Hd + jcell] = c1r;
}

// ---------------- deferred attention ----------------
__global__ void k_attn_post(const float* __restrict__ ctxs) {
    __shared__ __align__(16) float hsm[1024];
    __shared__ float ssm[64], wsm[64];
    int bx = blockIdx.x, tid = threadIdx.x;
    int t = bx >> 5, bb = bx & 31;
    const float* h1 = g_h1all + (size_t)(t * Bz + bb) * Hd;
    for (int i = tid; i < 1024; i += 256) hsm[i] = h1[i];
    __syncthreads();
    int wq = tid >> 5, lane = tid & 31;
    const float4* h4 = (const float4*)hsm;
#pragma unroll
    for (int si = 0; si < 8; si++) {
        int s = wq * 8 + si;
        const float4* cw4 = (const float4*)(g_Cw + (size_t)(bb * Ss + s) * Hd);
        float a = 0.f;
#pragma unroll
        for (int i = 0; i < 8; i++) {
            float4 cv = cw4[lane + 32 * i];
            float4 hv = h4[lane + 32 * i];
            a += cv.x * hv.x + cv.y * hv.y + cv.z * hv.z + cv.w * hv.w;
        }
#pragma unroll
        for (int o = 16; o; o >>= 1) a += __shfl_xor_sync(~0u, a, o);
        if (!lane) ssm[s] = a + g_sb[bb * Ss + s];
    }
    __syncthreads();
    if (tid == 0) {
        float mx = ssm[0];
        for (int s = 1; s < 64; s++) mx = fmaxf(mx, ssm[s]);
        float sum = 0.f;
        for (int s = 0; s < 64; s++) { float e = expf(ssm[s] - mx); wsm[s] = e; sum += e; }
        float inv = 1.f / sum;
        for (int s = 0; s < 64; s++) wsm[s] *= inv;
    }
    __syncthreads();
    const float4* c4 = (const float4*)(ctxs + (size_t)bb * Ss * Hd);
    float4 acc = make_float4(0.f, 0.f, 0.f, 0.f);
    for (int s = 0; s < 64; s++) {
        float wv = wsm[s];
        float4 cv = c4[s * 256 + tid];
        acc.x += wv * cv.x; acc.y += wv * cv.y; acc.z += wv * cv.z; acc.w += wv * cv.w;
    }
    ((float4*)(g_ctxall + (size_t)(t * Bz + bb) * Hd))[tid] = acc;
}

// ---------------- out = tanh([ctx, h1] @ Wout^T + b) ----------
__global__ void k_out_big(const float* __restrict__ Wout, const float* __restrict__ bout,
                          float* __restrict__ out) {
    __shared__ __align__(16) float Asm[32 * 33];
    __shared__ __align__(16) float Wsm[32 * 68];
    int tid = threadIdx.x;
    int m0 = blockIdx.x * 32, n0 = blockIdx.y * 64;
    int m = tid >> 3, q = tid & 7;
    u64 acc0 = 0, acc1 = 0, acc2 = 0, acc3 = 0;
    for (int k0 = 0; k0 < 2 * Hd; k0 += 32) {
        for (int idx = tid; idx < 1024; idx += 256) {
            int mm = idx >> 5, kk = idx & 31;
            int k = k0 + kk;
            float v = (k < Hd) ? g_ctxall[(size_t)(m0 + mm) * Hd + k]
                               : g_h1all[(size_t)(m0 + mm) * Hd + k - Hd];
            Asm[kk * 33 + mm] = v;
        }
        for (int idx = tid; idx < 2048; idx += 256) {
            int nn = idx >> 5, kk = idx & 31;
            Wsm[kk * 68 + nn] = Wout[(size_t)(n0 + nn) * (2 * Hd) + k0 + kk];
        }
        __syncthreads();
#pragma unroll
        for (int kk = 0; kk < 32; kk++) {
            u64 ad = dup2(Asm[kk * 33 + m]);
            const ulonglong2* wp = (const ulonglong2*)(Wsm + kk * 68 + q * 8);
            ulonglong2 w0 = wp[0], w1 = wp[1];
            acc0 = ffma2(w0.x, ad, acc0);
            acc1 = ffma2(w0.y, ad, acc1);
            acc2 = ffma2(w1.x, ad, acc2);
            acc3 = ffma2(w1.y, ad, acc3);
        }
        __syncthreads();
    }
    int row = m0 + m, nb = n0 + q * 8;
    float* dst = out + (size_t)row * Hd + nb;
    u64 accs[4] = {acc0, acc1, acc2, acc3};
#pragma unroll
    for (int j = 0; j < 4; j++) {
        float2 v = unpack2(accs[j]);
        int n = nb + 2 * j;
        dst[2 * j]     = tanhf(v.x + bout[n]);
        dst[2 * j + 1] = tanhf(v.y + bout[n + 1]);
    }
}

__global__ void k_tail(float* __restrict__ out, int out_size) {
    int idx = blockIdx.x * 256 + threadIdx.x;
    int base = Tt * Bz * Hd;
    if (idx < 2 * Bz * Hd) {
        int l = idx >> 15, r = idx & 32767;
        int o = base + idx;
        if (o < out_size) out[o] = g_h[l][0][r];
    } else {
        int jx = idx - 2 * Bz * Hd;
        int l = jx >> 15, r = jx & 32767;
        int o = base + 2 * Bz * Hd + jx;
        if (o < out_size) out[o] = g_c[l][r];
    }
}

extern "C" void kernel_launch(void* const* d_in, const int* in_sizes, int n_in,
                              void* d_out, int out_size) {
    const int*   tokens   = (const int*)d_in[0];
    const float* h0       = (const float*)d_in[1];
    const float* c0       = (const float*)d_in[2];
    const float* contexts = (const float*)d_in[3];
    const float* emb      = (const float*)d_in[4];
    const float* W_ih     = (const float*)d_in[5];
    const float* W_hh     = (const float*)d_in[6];
    const float* b_ih     = (const float*)d_in[7];
    const float* b_hh     = (const float*)d_in[8];
    const float* W_in     = (const float*)d_in[9];
    const float* b_in     = (const float*)d_in[10];
    const float* W_out    = (const float*)d_in[11];
    const float* b_out    = (const float*)d_in[12];
    float* out = (float*)d_out;

    cudaFuncSetAttribute(k_steps, cudaFuncAttributeMaxDynamicSharedMemorySize,
                         SM_TOT * 4);

    k_setup<<<3 * NB, 256>>>(h0, c0, contexts, b_in, W_ih, W_hh);          // 1
    k_x0<<<dim3(64, 64), 256>>>(tokens, emb, W_ih, b_ih, b_hh);            // 2
    k_cw<<<dim3(64, 16), 256>>>(contexts, W_in);                           // 3
    k_steps<<<NB, 256, SM_TOT * 4>>>(b_ih, b_hh);                          // 4 <- ncu
    k_attn_post<<<Tt * Bz, 256>>>(contexts);                               // 5
    k_out_big<<<dim3(64, 16), 256>>>(W_out, b_out, out);                   // 6
    k_tail<<<512, 256>>>(out, out_size);                                   // 7
}